// round 8
// baseline (speedup 1.0000x reference)
#include <cuda_runtime.h>
#include <cstdint>

#define T_ 64
#define B_ 8
#define S_ 512
#define H_ 512
#define TBH (T_*B_*H_)
#define BSH (B_*S_*H_)

// Scratch (no device allocations allowed).
__device__ float g_enc[BSH];             // tanh(enc + cov*wcov), [B,S,H]
__device__ float g_a1 [TBH];             // dec@Wq + bq, rows r=t*B+b
__device__ float g_a2 [BSH];             // enc'@Wc, rows b*S+s
__device__ float g_E2 [BSH];             // enc'@Wo1, rows b*S+s
__device__ float g_cp [4][TBH];          // align@E2 split-K partials
__device__ float g_op [4][TBH];          // dec@Wo2 partials (planes 2,3 used)

__device__ __forceinline__ float ex2f_(float x){ float y; asm("ex2.approx.f32 %0, %1;" : "=f"(y) : "f"(x)); return y; }
__device__ __forceinline__ float rcpf_(float x){ float y; asm("rcp.approx.f32 %0, %1;" : "=f"(y) : "f"(x)); return y; }
__device__ __forceinline__ float tanhf_hw(float x){ float y; asm("tanh.approx.f32 %0, %1;" : "=f"(y) : "f"(x)); return y; }

__device__ __forceinline__ float fast_tanh(float x){
    x = fminf(fmaxf(x, -15.0f), 15.0f);
    float e = ex2f_(x * 2.8853900817779268f);
    return (e - 1.0f) * rcpf_(e + 1.0f);
}

// ---- packed f32x2 helpers ----
__device__ __forceinline__ void ffma2(uint64_t& d, uint64_t a, uint64_t b){
    asm("fma.rn.f32x2 %0, %1, %2, %0;" : "+l"(d) : "l"(a), "l"(b));
}
__device__ __forceinline__ uint64_t pk2dup(float a){
    uint64_t r; asm("mov.b64 %0, {%1, %1};" : "=l"(r) : "f"(a)); return r;
}
__device__ __forceinline__ float2 upk2(uint64_t p){
    float2 f; asm("mov.b64 {%0, %1}, %2;" : "=f"(f.x), "=f"(f.y) : "l"(p)); return f;
}

// -------- enc' = tanh(enc + cov*wcov), [S,B,H] -> [B,S,H] --------
__global__ void prep_enc_kernel(const float* __restrict__ enc,
                                const float* __restrict__ cov,
                                const float* __restrict__ wcov)
{
    int idx = blockIdx.x * 256 + threadIdx.x;
    int h  = idx & (H_-1);
    int bs = idx >> 9;
    int s  = bs & (S_-1);
    int b  = bs >> 9;
    float e = enc[(s*B_ + b)*H_ + h];
    g_enc[idx] = fast_tanh(fmaf(cov[b*S_ + s], wcov[h], e));
}

// -------- shared 128x128x8 f32x2 macro-body (double-buffered) --------
__device__ __forceinline__ void gemm128_body(
    const float* __restrict__ A, const float* __restrict__ B,
    float* __restrict__ C, const float* __restrict__ bias,
    int rowBase, int colBase)
{
    __shared__ float As[2][8][128];
    __shared__ float Bs[2][8][128];

    const int tid = threadIdx.x;
    const int tx = tid & 15, ty = tid >> 4;
    const int aRow = tid >> 1,  aCol = (tid & 1) << 2;
    const int bRow = tid >> 5,  bCol = (tid & 31) << 2;

    const float* Aptr = A + (long)(rowBase + aRow)*H_ + aCol;
    const float* Bptr = B + (long)bRow*H_ + colBase + bCol;

    uint64_t acc[8][4];
    #pragma unroll
    for (int i = 0; i < 8; i++)
        #pragma unroll
        for (int j = 0; j < 4; j++) acc[i][j] = 0ull;

    {
        float4 av = *(const float4*)(Aptr);
        As[0][aCol+0][aRow] = av.x; As[0][aCol+1][aRow] = av.y;
        As[0][aCol+2][aRow] = av.z; As[0][aCol+3][aRow] = av.w;
        *(float4*)(&Bs[0][bRow][bCol]) = *(const float4*)(Bptr);
    }
    __syncthreads();

    const int KT = H_ >> 3;    // 64
    for (int kt = 0; kt < KT; kt++) {
        const int cur = kt & 1;
        float4 av, bv;
        const bool more = (kt + 1 < KT);
        if (more) {
            av = *(const float4*)(Aptr + (kt+1)*8);
            bv = *(const float4*)(Bptr + (long)(kt+1)*8*H_);
        }
        #pragma unroll
        for (int k = 0; k < 8; k++) {
            float4 a0 = *(const float4*)(&As[cur][k][ty << 2]);
            float4 a1 = *(const float4*)(&As[cur][k][(ty << 2) + 64]);
            ulonglong2 bb0 = *(const ulonglong2*)(&Bs[cur][k][tx << 2]);
            ulonglong2 bb1 = *(const ulonglong2*)(&Bs[cur][k][(tx << 2) + 64]);
            uint64_t br[4] = {bb0.x, bb0.y, bb1.x, bb1.y};
            uint64_t pr[8] = {pk2dup(a0.x), pk2dup(a0.y), pk2dup(a0.z), pk2dup(a0.w),
                              pk2dup(a1.x), pk2dup(a1.y), pk2dup(a1.z), pk2dup(a1.w)};
            #pragma unroll
            for (int i = 0; i < 8; i++)
                #pragma unroll
                for (int j = 0; j < 4; j++)
                    ffma2(acc[i][j], pr[i], br[j]);
        }
        if (more) {
            const int nxt = cur ^ 1;
            As[nxt][aCol+0][aRow] = av.x; As[nxt][aCol+1][aRow] = av.y;
            As[nxt][aCol+2][aRow] = av.z; As[nxt][aCol+3][aRow] = av.w;
            *(float4*)(&Bs[nxt][bRow][bCol]) = bv;
        }
        __syncthreads();
    }

    #pragma unroll
    for (int ih = 0; ih < 2; ih++) {
        #pragma unroll
        for (int i = 0; i < 4; i++) {
            int r = rowBase + ih*64 + (ty << 2) + i;
            #pragma unroll
            for (int jh = 0; jh < 2; jh++) {
                float2 p0 = upk2(acc[ih*4+i][jh*2+0]);
                float2 p1 = upk2(acc[ih*4+i][jh*2+1]);
                float4 o = make_float4(p0.x, p0.y, p1.x, p1.y);
                int col = colBase + jh*64 + (tx << 2);
                if (bias) {
                    float4 bvv = *(const float4*)(bias + col);
                    o.x += bvv.x; o.y += bvv.y; o.z += bvv.z; o.w += bvv.w;
                }
                *(float4*)(C + (long)r*H_ + col) = o;
            }
        }
    }
}

// blocks 0..127: a2 = enc'@Wc ; blocks 128..143: a1 = dec@Wq + bq
__global__ __launch_bounds__(256)
void qc_gemm_kernel(const float* __restrict__ Wc,
                    const float* __restrict__ dec, const float* __restrict__ Wq,
                    const float* __restrict__ bq)
{
    int id = blockIdx.x;
    if (id < 128)
        gemm128_body(g_enc, Wc, g_a2, nullptr, (id >> 2)*128, (id & 3)*128);
    else {
        int j = id - 128;
        gemm128_body(dec, Wq, g_a1, bq, (j >> 2)*128, (j & 3)*128);
    }
}

// E2 = enc'@Wo1 (M=4096, N=512, K=512) — runs concurrently with scores.
__global__ __launch_bounds__(256)
void e2_gemm_kernel(const float* __restrict__ Wo)
{
    gemm128_body(g_enc, Wo, g_E2, nullptr, (int)blockIdx.y*128, (int)blockIdx.x*128);
}

// -------- 64x64 split-K tile, double-buffered, f32x2 --------
template<int KCHUNK>
__device__ __forceinline__ void tile64_body(
    const float* __restrict__ A, long ldaRow,
    const float* __restrict__ Bm,
    float* __restrict__ C, long ldcRow)
{
    __shared__ float As[2][16][64];
    __shared__ float Bs[2][16][64];

    const int tid = threadIdx.x;
    const int tx = tid & 15, ty = tid >> 4;
    const int aRow = tid >> 2, aCol = (tid & 3) << 2;
    const int bRow = tid >> 4, bCol = (tid & 15) << 2;

    uint64_t acc[4][2];
    #pragma unroll
    for (int i = 0; i < 4; i++) { acc[i][0] = 0ull; acc[i][1] = 0ull; }

    float4 av = *(const float4*)(A + (long)aRow*ldaRow + aCol);
    float4 bv = *(const float4*)(Bm + (long)bRow*H_ + bCol);
    int buf = 0;

    for (int k0 = 0; k0 < KCHUNK; k0 += 16) {
        As[buf][aCol+0][aRow] = av.x;
        As[buf][aCol+1][aRow] = av.y;
        As[buf][aCol+2][aRow] = av.z;
        As[buf][aCol+3][aRow] = av.w;
        *(float4*)(&Bs[buf][bRow][bCol]) = bv;
        __syncthreads();

        if (k0 + 16 < KCHUNK) {
            av = *(const float4*)(A + (long)aRow*ldaRow + k0 + 16 + aCol);
            bv = *(const float4*)(Bm + (long)(k0 + 16 + bRow)*H_ + bCol);
        }

        #pragma unroll
        for (int k = 0; k < 16; k++) {
            float4 a = *(const float4*)(&As[buf][k][ty << 2]);
            ulonglong2 bb = *(const ulonglong2*)(&Bs[buf][k][tx << 2]);
            uint64_t pr[4] = {pk2dup(a.x), pk2dup(a.y), pk2dup(a.z), pk2dup(a.w)};
            #pragma unroll
            for (int i = 0; i < 4; i++) {
                ffma2(acc[i][0], pr[i], bb.x);
                ffma2(acc[i][1], pr[i], bb.y);
            }
        }
        __syncthreads();
        buf ^= 1;
    }

    #pragma unroll
    for (int i = 0; i < 4; i++) {
        float2 p0 = upk2(acc[i][0]);
        float2 p1 = upk2(acc[i][1]);
        float4 o = make_float4(p0.x, p0.y, p1.x, p1.y);
        *(float4*)(C + (long)((ty << 2) + i)*ldcRow + (tx << 2)) = o;
    }
}

// align@E2 partials: grid (8 nT, 8 b, 4 kz), K=128 each
__global__ __launch_bounds__(256)
void ce_splitk_kernel(const float* __restrict__ align)
{
    const int nT = blockIdx.x, b = blockIdx.y, kz = blockIdx.z;
    const float* A  = align + (long)b*S_ + kz*128;
    const float* Bm = g_E2 + ((long)b*S_ + kz*128)*H_ + nT*64;
    float* C = g_cp[kz] + (long)b*H_ + nT*64;
    tile64_body<128>(A, (long)B_*S_, Bm, C, (long)B_*H_);
}

// dec@Wo2 partials (planes 2,3): inputs only -> side stream, overlaps prep/qc
__global__ __launch_bounds__(256)
void out_splitk_d_kernel(const float* __restrict__ dec, const float* __restrict__ Wo)
{
    const int nT = blockIdx.x, mT = blockIdx.y, kz = blockIdx.z + 2;
    const float* A  = dec + (kz-2)*256 + (long)mT*64*H_;
    const float* Bm = Wo + (long)(kz*256)*H_ + nT*64;
    float* C = g_op[kz] + (long)mT*64*H_ + nT*64;
    tile64_body<256>(A, (long)H_, Bm, C, (long)H_);
}

// attn_h = sum(cp[0..3]) + op[2] + op[3] + bo
__global__ void final_reduce_kernel(float* __restrict__ attn_h,
                                    const float* __restrict__ bo)
{
    int idx = (blockIdx.x * 256 + threadIdx.x) * 4;
    int hq = idx & (H_-1);
    float4 a = *(const float4*)(&g_cp[0][idx]);
    float4 b = *(const float4*)(&g_cp[1][idx]);
    float4 c = *(const float4*)(&g_cp[2][idx]);
    float4 d = *(const float4*)(&g_cp[3][idx]);
    float4 e = *(const float4*)(&g_op[2][idx]);
    float4 f = *(const float4*)(&g_op[3][idx]);
    float4 bb = *(const float4*)(bo + hq);
    float4 o = make_float4(a.x+b.x+c.x+d.x+e.x+f.x+bb.x,
                           a.y+b.y+c.y+d.y+e.y+f.y+bb.y,
                           a.z+b.z+c.z+d.z+e.z+f.z+bb.z,
                           a.w+b.w+c.w+d.w+e.w+f.w+bb.w);
    *(float4*)(attn_h + idx) = o;
}

// -------- scores + softmax, 4 t-rows per block, prefetched s-tiles --------
__global__ __launch_bounds__(512)
void scores_softmax_kernel(const float* __restrict__ v,
                           float* __restrict__ align_out)
{
    const int tg = blockIdx.x;
    const int b  = blockIdx.y;
    const int tid = threadIdx.x;
    const int warp = tid >> 5, lane = tid & 31;

    __shared__ float sa1[4][H_];
    __shared__ float ssc[4][S_];
    __shared__ float sred[17];

    #pragma unroll
    for (int i = 0; i < 4; i++)
        sa1[i][tid] = g_a1[((tg*4 + i)*B_ + b)*H_ + tid];

    float4 v0 = *(const float4*)(v + lane*4);
    float4 v1 = *(const float4*)(v + lane*4 + 128);
    float4 v2 = *(const float4*)(v + lane*4 + 256);
    float4 v3 = *(const float4*)(v + lane*4 + 384);
    __syncthreads();

    const float* a2base = g_a2 + (long)b*S_*H_ + lane*4;

    float4 x[4];
    {
        const float* p = a2base + (long)warp*H_;
        x[0] = *(const float4*)(p);
        x[1] = *(const float4*)(p + 128);
        x[2] = *(const float4*)(p + 256);
        x[3] = *(const float4*)(p + 384);
    }

    for (int s = warp; s < S_; s += 16) {
        float4 y[4];
        const int sn = s + 16;
        if (sn < S_) {
            const float* p = a2base + (long)sn*H_;
            y[0] = *(const float4*)(p);
            y[1] = *(const float4*)(p + 128);
            y[2] = *(const float4*)(p + 256);
            y[3] = *(const float4*)(p + 384);
        }

        #pragma unroll
        for (int i = 0; i < 4; i++) {
            float4 a0 = *(const float4*)(&sa1[i][lane*4]);
            float4 a1 = *(const float4*)(&sa1[i][lane*4 + 128]);
            float4 a2 = *(const float4*)(&sa1[i][lane*4 + 256]);
            float4 a3 = *(const float4*)(&sa1[i][lane*4 + 384]);
            float acc = 0.0f;
            acc = fmaf(tanhf_hw(a0.x + x[0].x), v0.x, acc);
            acc = fmaf(tanhf_hw(a0.y + x[0].y), v0.y, acc);
            acc = fmaf(tanhf_hw(a0.z + x[0].z), v0.z, acc);
            acc = fmaf(tanhf_hw(a0.w + x[0].w), v0.w, acc);
            acc = fmaf(tanhf_hw(a1.x + x[1].x), v1.x, acc);
            acc = fmaf(tanhf_hw(a1.y + x[1].y), v1.y, acc);
            acc = fmaf(tanhf_hw(a1.z + x[1].z), v1.z, acc);
            acc = fmaf(tanhf_hw(a1.w + x[1].w), v1.w, acc);
            acc = fmaf(tanhf_hw(a2.x + x[2].x), v2.x, acc);
            acc = fmaf(tanhf_hw(a2.y + x[2].y), v2.y, acc);
            acc = fmaf(tanhf_hw(a2.z + x[2].z), v2.z, acc);
            acc = fmaf(tanhf_hw(a2.w + x[2].w), v2.w, acc);
            acc = fmaf(tanhf_hw(a3.x + x[3].x), v3.x, acc);
            acc = fmaf(tanhf_hw(a3.y + x[3].y), v3.y, acc);
            acc = fmaf(tanhf_hw(a3.z + x[3].z), v3.z, acc);
            acc = fmaf(tanhf_hw(a3.w + x[3].w), v3.w, acc);
            #pragma unroll
            for (int o = 16; o > 0; o >>= 1)
                acc += __shfl_xor_sync(0xffffffffu, acc, o);
            if (lane == 0) ssc[i][s] = acc;
        }
        x[0] = y[0]; x[1] = y[1]; x[2] = y[2]; x[3] = y[3];
    }
    __syncthreads();

    #pragma unroll
    for (int i = 0; i < 4; i++) {
        float xx = ssc[i][tid];
        float m = xx;
        #pragma unroll
        for (int o = 16; o > 0; o >>= 1) m = fmaxf(m, __shfl_xor_sync(0xffffffffu, m, o));
        if (lane == 0) sred[warp] = m;
        __syncthreads();
        if (warp == 0) {
            float mm = (lane < 16) ? sred[lane] : -1e30f;
            #pragma unroll
            for (int o = 8; o > 0; o >>= 1) mm = fmaxf(mm, __shfl_xor_sync(0xffffffffu, mm, o));
            if (lane == 0) sred[16] = mm;
        }
        __syncthreads();
        const float mx = sred[16];
        float e = ex2f_((xx - mx) * 1.4426950408889634f);
        float ssum = e;
        #pragma unroll
        for (int o = 16; o > 0; o >>= 1) ssum += __shfl_xor_sync(0xffffffffu, ssum, o);
        __syncthreads();
        if (lane == 0) sred[warp] = ssum;
        __syncthreads();
        if (warp == 0) {
            float t = (lane < 16) ? sred[lane] : 0.0f;
            #pragma unroll
            for (int o = 8; o > 0; o >>= 1) t += __shfl_xor_sync(0xffffffffu, t, o);
            if (lane == 0) sred[16] = t;
        }
        __syncthreads();
        float p = e * rcpf_(sred[16]);
        align_out[(long)((tg*4 + i)*B_ + b)*S_ + tid] = p;
        __syncthreads();
    }
}

extern "C" void kernel_launch(void* const* d_in, const int* in_sizes, int n_in,
                              void* d_out, int out_size)
{
    const float* dec  = (const float*)d_in[0];
    const float* enc  = (const float*)d_in[1];
    const float* cov  = (const float*)d_in[2];
    const float* Wq   = (const float*)d_in[3];
    const float* bq   = (const float*)d_in[4];
    const float* Wc   = (const float*)d_in[5];
    const float* v    = (const float*)d_in[6];
    const float* Wo   = (const float*)d_in[7];
    const float* bo   = (const float*)d_in[8];
    const float* wcov = (const float*)d_in[9];

    float* attn_h = (float*)d_out;
    float* align  = (float*)d_out + TBH;

    static cudaStream_t s1 = nullptr;
    static cudaEvent_t evFork = nullptr, evQC = nullptr, evE2 = nullptr;
    if (!s1) {
        cudaStreamCreateWithFlags(&s1, cudaStreamNonBlocking);
        cudaEventCreateWithFlags(&evFork, cudaEventDisableTiming);
        cudaEventCreateWithFlags(&evQC, cudaEventDisableTiming);
        cudaEventCreateWithFlags(&evE2, cudaEventDisableTiming);
    }

    // Side stream: dec@Wo2 partials (inputs only), then E2 after qc completes.
    cudaEventRecord(evFork, 0);
    cudaStreamWaitEvent(s1, evFork, 0);
    out_splitk_d_kernel<<<dim3(8, 8, 2), 256, 0, s1>>>(dec, Wo);

    // Main: prep -> qc (a1+a2).
    prep_enc_kernel<<<BSH/256, 256>>>(enc, cov, wcov);
    qc_gemm_kernel<<<144, 256>>>(Wc, dec, Wq, bq);
    cudaEventRecord(evQC, 0);

    // Side: E2 = enc'@Wo1 — overlaps the MUFU-bound scores kernel.
    cudaStreamWaitEvent(s1, evQC, 0);
    e2_gemm_kernel<<<dim3(4, 32), 256, 0, s1>>>(Wo);
    cudaEventRecord(evE2, s1);

    // Main: scores + softmax (concurrent with E2).
    scores_softmax_kernel<<<dim3(16, 8), 512>>>(v, align);

    // Join, then align@E2 partials and final 6-way reduce (+bias).
    cudaStreamWaitEvent(0, evE2, 0);
    ce_splitk_kernel<<<dim3(8, 8, 4), 256>>>(align);
    final_reduce_kernel<<<TBH/1024, 256>>>(attn_h, bo);
}

// round 9
// speedup vs baseline: 1.5321x; 1.5321x over previous
#include <cuda_runtime.h>
#include <cstdint>

#define T_ 64
#define B_ 8
#define S_ 512
#define H_ 512
#define TBH (T_*B_*H_)
#define BSH (B_*S_*H_)

// Scratch (no device allocations allowed).
__device__ float g_a1 [TBH];             // dec@Wq + bq, rows r=t*B+b
__device__ float g_a2 [BSH];             // enc'@Wc, rows b*S+s
__device__ float g_cp [4][TBH];          // c = align@enc' split-K partials
__device__ float g_op [8][TBH];          // out split-K partials (8 x K=128)

__device__ __forceinline__ float ex2f_(float x){ float y; asm("ex2.approx.f32 %0, %1;" : "=f"(y) : "f"(x)); return y; }
__device__ __forceinline__ float rcpf_(float x){ float y; asm("rcp.approx.f32 %0, %1;" : "=f"(y) : "f"(x)); return y; }
__device__ __forceinline__ float tanhf_hw(float x){ float y; asm("tanh.approx.f32 %0, %1;" : "=f"(y) : "f"(x)); return y; }

// accurate tanh (~1e-6): used for enc' recompute inside GEMM loaders (MUFU idle there)
__device__ __forceinline__ float fast_tanh(float x){
    x = fminf(fmaxf(x, -15.0f), 15.0f);
    float e = ex2f_(x * 2.8853900817779268f);
    return (e - 1.0f) * rcpf_(e + 1.0f);
}

// ---- packed f32x2 helpers ----
__device__ __forceinline__ void ffma2(uint64_t& d, uint64_t a, uint64_t b){
    asm("fma.rn.f32x2 %0, %1, %2, %0;" : "+l"(d) : "l"(a), "l"(b));
}
__device__ __forceinline__ uint64_t pk2dup(float a){
    uint64_t r; asm("mov.b64 %0, {%1, %1};" : "=l"(r) : "f"(a)); return r;
}
__device__ __forceinline__ float2 upk2(uint64_t p){
    float2 f; asm("mov.b64 {%0, %1}, %2;" : "=f"(f.x), "=f"(f.y) : "l"(p)); return f;
}

// -------- 128x128x8 f32x2 body, double-buffered; optional fused tanh on A --------
// Aptr: per-thread base (row resolved, includes aCol), row-contiguous in k.
template<bool TANHA>
__device__ __forceinline__ void gemm128_body(
    const float* __restrict__ Aptr, const float* __restrict__ B,
    float* __restrict__ C, const float* __restrict__ bias,
    const float* __restrict__ wcov, float cv,
    int rowBase, int colBase)
{
    __shared__ float As[2][8][128];
    __shared__ float Bs[2][8][128];

    const int tid = threadIdx.x;
    const int tx = tid & 15, ty = tid >> 4;
    const int aRow = tid >> 1,  aCol = (tid & 1) << 2;
    const int bRow = tid >> 5,  bCol = (tid & 31) << 2;

    const float* Bptr = B + (long)bRow*H_ + colBase + bCol;

    uint64_t acc[8][4];
    #pragma unroll
    for (int i = 0; i < 8; i++)
        #pragma unroll
        for (int j = 0; j < 4; j++) acc[i][j] = 0ull;

    float4 av = *(const float4*)(Aptr);
    float4 wv = TANHA ? *(const float4*)(wcov + aCol) : make_float4(0,0,0,0);
    {
        if (TANHA) {
            av.x = fast_tanh(fmaf(cv, wv.x, av.x));
            av.y = fast_tanh(fmaf(cv, wv.y, av.y));
            av.z = fast_tanh(fmaf(cv, wv.z, av.z));
            av.w = fast_tanh(fmaf(cv, wv.w, av.w));
        }
        As[0][aCol+0][aRow] = av.x; As[0][aCol+1][aRow] = av.y;
        As[0][aCol+2][aRow] = av.z; As[0][aCol+3][aRow] = av.w;
        *(float4*)(&Bs[0][bRow][bCol]) = *(const float4*)(Bptr);
    }
    __syncthreads();

    const int KT = H_ >> 3;    // 64
    for (int kt = 0; kt < KT; kt++) {
        const int cur = kt & 1;
        float4 bv;
        const bool more = (kt + 1 < KT);
        if (more) {
            av = *(const float4*)(Aptr + (kt+1)*8);
            if (TANHA) wv = *(const float4*)(wcov + (kt+1)*8 + aCol);
            bv = *(const float4*)(Bptr + (long)(kt+1)*8*H_);
        }
        #pragma unroll
        for (int k = 0; k < 8; k++) {
            float4 a0 = *(const float4*)(&As[cur][k][ty << 2]);
            float4 a1 = *(const float4*)(&As[cur][k][(ty << 2) + 64]);
            ulonglong2 bb0 = *(const ulonglong2*)(&Bs[cur][k][tx << 2]);
            ulonglong2 bb1 = *(const ulonglong2*)(&Bs[cur][k][(tx << 2) + 64]);
            uint64_t br[4] = {bb0.x, bb0.y, bb1.x, bb1.y};
            uint64_t pr[8] = {pk2dup(a0.x), pk2dup(a0.y), pk2dup(a0.z), pk2dup(a0.w),
                              pk2dup(a1.x), pk2dup(a1.y), pk2dup(a1.z), pk2dup(a1.w)};
            #pragma unroll
            for (int i = 0; i < 8; i++)
                #pragma unroll
                for (int j = 0; j < 4; j++)
                    ffma2(acc[i][j], pr[i], br[j]);
        }
        if (more) {
            const int nxt = cur ^ 1;
            if (TANHA) {
                av.x = fast_tanh(fmaf(cv, wv.x, av.x));
                av.y = fast_tanh(fmaf(cv, wv.y, av.y));
                av.z = fast_tanh(fmaf(cv, wv.z, av.z));
                av.w = fast_tanh(fmaf(cv, wv.w, av.w));
            }
            As[nxt][aCol+0][aRow] = av.x; As[nxt][aCol+1][aRow] = av.y;
            As[nxt][aCol+2][aRow] = av.z; As[nxt][aCol+3][aRow] = av.w;
            *(float4*)(&Bs[nxt][bRow][bCol]) = bv;
        }
        __syncthreads();
    }

    #pragma unroll
    for (int ih = 0; ih < 2; ih++) {
        #pragma unroll
        for (int i = 0; i < 4; i++) {
            int r = rowBase + ih*64 + (ty << 2) + i;
            #pragma unroll
            for (int jh = 0; jh < 2; jh++) {
                float2 p0 = upk2(acc[ih*4+i][jh*2+0]);
                float2 p1 = upk2(acc[ih*4+i][jh*2+1]);
                float4 o = make_float4(p0.x, p0.y, p1.x, p1.y);
                int col = colBase + jh*64 + (tx << 2);
                if (bias) {
                    float4 bvv = *(const float4*)(bias + col);
                    o.x += bvv.x; o.y += bvv.y; o.z += bvv.z; o.w += bvv.w;
                }
                *(float4*)(C + (long)r*H_ + col) = o;
            }
        }
    }
}

// blocks 0..127: a2 = tanh(enc+cov*wcov)@Wc ; blocks 128..143: a1 = dec@Wq + bq
__global__ __launch_bounds__(256)
void qc_gemm_kernel(const float* __restrict__ enc, const float* __restrict__ cov,
                    const float* __restrict__ wcov, const float* __restrict__ Wc,
                    const float* __restrict__ dec, const float* __restrict__ Wq,
                    const float* __restrict__ bq)
{
    int id = blockIdx.x;
    const int aCol = (threadIdx.x & 1) << 2;
    if (id < 128) {
        int rowBase = (id >> 2)*128, colBase = (id & 3)*128;
        int r = rowBase + (threadIdx.x >> 1);
        int b = r >> 9, s = r & 511;
        const float* Aptr = enc + ((long)s*B_ + b)*H_ + aCol;   // raw enc [s][b][h]
        float cv = cov[b*S_ + s];
        gemm128_body<true>(Aptr, Wc, g_a2, nullptr, wcov, cv, rowBase, colBase);
    } else {
        int j = id - 128;
        int rowBase = (j >> 2)*128, colBase = (j & 3)*128;
        const float* Aptr = dec + (long)(rowBase + (threadIdx.x >> 1))*H_ + aCol;
        gemm128_body<false>(Aptr, Wq, g_a1, bq, nullptr, 0.0f, rowBase, colBase);
    }
}

// -------- 64x64 split-K tile (K=128), double-buffered, f32x2; plain B --------
// SUMC: A-load sums 4 planes of g_cp (stride TBH).
template<bool SUMC>
__device__ __forceinline__ void tile64_plain(
    const float* __restrict__ A, long ldaRow,
    const float* __restrict__ Bm, long ldbRow,
    float* __restrict__ C, long ldcRow)
{
    __shared__ float As[2][16][64];
    __shared__ float Bs[2][16][64];

    const int tid = threadIdx.x;
    const int tx = tid & 15, ty = tid >> 4;
    const int aRow = tid >> 2, aCol = (tid & 3) << 2;
    const int bRow = tid >> 4, bCol = (tid & 15) << 2;

    uint64_t acc[4][2];
    #pragma unroll
    for (int i = 0; i < 4; i++) { acc[i][0] = 0ull; acc[i][1] = 0ull; }

    auto loadA = [&](int k0) -> float4 {
        const float* p = A + (long)aRow*ldaRow + k0 + aCol;
        float4 v = *(const float4*)p;
        if (SUMC) {
            float4 v1 = *(const float4*)(p + (long)TBH);
            float4 v2 = *(const float4*)(p + 2*(long)TBH);
            float4 v3 = *(const float4*)(p + 3*(long)TBH);
            v.x += v1.x + v2.x + v3.x; v.y += v1.y + v2.y + v3.y;
            v.z += v1.z + v2.z + v3.z; v.w += v1.w + v2.w + v3.w;
        }
        return v;
    };

    float4 av = loadA(0);
    float4 bv = *(const float4*)(Bm + (long)bRow*ldbRow + bCol);
    int buf = 0;

    for (int k0 = 0; k0 < 128; k0 += 16) {
        As[buf][aCol+0][aRow] = av.x;
        As[buf][aCol+1][aRow] = av.y;
        As[buf][aCol+2][aRow] = av.z;
        As[buf][aCol+3][aRow] = av.w;
        *(float4*)(&Bs[buf][bRow][bCol]) = bv;
        __syncthreads();

        if (k0 + 16 < 128) {
            av = loadA(k0 + 16);
            bv = *(const float4*)(Bm + (long)(k0 + 16 + bRow)*ldbRow + bCol);
        }

        #pragma unroll
        for (int k = 0; k < 16; k++) {
            float4 a = *(const float4*)(&As[buf][k][ty << 2]);
            ulonglong2 bb = *(const ulonglong2*)(&Bs[buf][k][tx << 2]);
            uint64_t pr[4] = {pk2dup(a.x), pk2dup(a.y), pk2dup(a.z), pk2dup(a.w)};
            #pragma unroll
            for (int i = 0; i < 4; i++) {
                ffma2(acc[i][0], pr[i], bb.x);
                ffma2(acc[i][1], pr[i], bb.y);
            }
        }
        __syncthreads();
        buf ^= 1;
    }

    #pragma unroll
    for (int i = 0; i < 4; i++) {
        float2 p0 = upk2(acc[i][0]);
        float2 p1 = upk2(acc[i][1]);
        float4 o = make_float4(p0.x, p0.y, p1.x, p1.y);
        *(float4*)(C + (long)((ty << 2) + i)*ldcRow + (tx << 2)) = o;
    }
}

// c partials with fused enc' recompute on the B side: grid (8 nT, 8 b, 4 kz)
__global__ __launch_bounds__(256)
void c_splitk_kernel(const float* __restrict__ align, const float* __restrict__ enc,
                     const float* __restrict__ cov, const float* __restrict__ wcov)
{
    const int nT = blockIdx.x, b = blockIdx.y, kz = blockIdx.z;
    const int s0 = kz*128;

    __shared__ float As[2][16][64];
    __shared__ float Bs[2][16][64];

    const int tid = threadIdx.x;
    const int tx = tid & 15, ty = tid >> 4;
    const int aRow = tid >> 2, aCol = (tid & 3) << 2;
    const int bRow = tid >> 4, bCol = (tid & 15) << 2;

    const float* A = align + (long)b*S_ + s0;          // row stride B_*S_
    const float* encB = enc + (long)b*H_ + nT*64 + bCol; // + s*(B_*H_)
    const float* covp = cov + b*S_ + s0;
    const float4 wv = *(const float4*)(wcov + nT*64 + bCol);
    float* C = g_cp[kz] + (long)b*H_ + nT*64;

    uint64_t acc[4][2];
    #pragma unroll
    for (int i = 0; i < 4; i++) { acc[i][0] = 0ull; acc[i][1] = 0ull; }

    auto loadB = [&](int k0) -> float4 {
        int s = k0 + bRow;
        float4 v = *(const float4*)(encB + (long)(s0 + s)*B_*H_ - (long)s0*B_*H_ + (long)s*B_*H_*0);
        // (simplified below — recomputed cleanly)
        return v;
    };
    (void)loadB;

    float4 av = *(const float4*)(A + (long)aRow*(B_*S_) + aCol);
    float cv = covp[bRow];
    float4 bv = *(const float4*)(encB + (long)(s0 + bRow)*B_*H_);
    int buf = 0;

    for (int k0 = 0; k0 < 128; k0 += 16) {
        As[buf][aCol+0][aRow] = av.x;
        As[buf][aCol+1][aRow] = av.y;
        As[buf][aCol+2][aRow] = av.z;
        As[buf][aCol+3][aRow] = av.w;
        {
            float4 t;
            t.x = fast_tanh(fmaf(cv, wv.x, bv.x));
            t.y = fast_tanh(fmaf(cv, wv.y, bv.y));
            t.z = fast_tanh(fmaf(cv, wv.z, bv.z));
            t.w = fast_tanh(fmaf(cv, wv.w, bv.w));
            *(float4*)(&Bs[buf][bRow][bCol]) = t;
        }
        __syncthreads();

        if (k0 + 16 < 128) {
            av = *(const float4*)(A + (long)aRow*(B_*S_) + k0 + 16 + aCol);
            cv = covp[k0 + 16 + bRow];
            bv = *(const float4*)(encB + (long)(s0 + k0 + 16 + bRow)*B_*H_);
        }

        #pragma unroll
        for (int k = 0; k < 16; k++) {
            float4 a = *(const float4*)(&As[buf][k][ty << 2]);
            ulonglong2 bb = *(const ulonglong2*)(&Bs[buf][k][tx << 2]);
            uint64_t pr[4] = {pk2dup(a.x), pk2dup(a.y), pk2dup(a.z), pk2dup(a.w)};
            #pragma unroll
            for (int i = 0; i < 4; i++) {
                ffma2(acc[i][0], pr[i], bb.x);
                ffma2(acc[i][1], pr[i], bb.y);
            }
        }
        __syncthreads();
        buf ^= 1;
    }

    #pragma unroll
    for (int i = 0; i < 4; i++) {
        float2 p0 = upk2(acc[i][0]);
        float2 p1 = upk2(acc[i][1]);
        float4 o = make_float4(p0.x, p0.y, p1.x, p1.y);
        *(float4*)(C + (long)((ty << 2) + i)*(B_*H_) + (tx << 2)) = o;
    }
}

// out partials, c-half (kz 0..3, K=128): A = on-the-fly sum of 4 c-partials
__global__ __launch_bounds__(256)
void out_splitk_c_kernel(const float* __restrict__ Wo)
{
    const int nT = blockIdx.x, mT = blockIdx.y, kz = blockIdx.z;   // {0..3}
    const float* A  = g_cp[0] + kz*128 + (long)mT*64*H_;
    const float* Bm = Wo + (long)(kz*128)*H_ + nT*64;
    float* C = g_op[kz] + (long)mT*64*H_ + nT*64;
    tile64_plain<true>(A, (long)H_, Bm, (long)H_, C, (long)H_);
}

// out partials, dec-half (kz 4..7, K=128): inputs only -> side stream
__global__ __launch_bounds__(256)
void out_splitk_d_kernel(const float* __restrict__ dec, const float* __restrict__ Wo)
{
    const int nT = blockIdx.x, mT = blockIdx.y, kz = blockIdx.z + 4;
    const float* A  = dec + (kz-4)*128 + (long)mT*64*H_;
    const float* Bm = Wo + (long)(kz*128)*H_ + nT*64;
    float* C = g_op[kz] + (long)mT*64*H_ + nT*64;
    tile64_plain<false>(A, (long)H_, Bm, (long)H_, C, (long)H_);
}

// attn_h = sum(op[0..7]) + bo
__global__ void final_reduce_kernel(float* __restrict__ attn_h,
                                    const float* __restrict__ bo)
{
    int idx = (blockIdx.x * 256 + threadIdx.x) * 4;
    int hq = idx & (H_-1);
    float4 o = *(const float4*)(bo + hq);
    #pragma unroll
    for (int p = 0; p < 8; p++) {
        float4 a = *(const float4*)(&g_op[p][idx]);
        o.x += a.x; o.y += a.y; o.z += a.z; o.w += a.w;
    }
    *(float4*)(attn_h + idx) = o;
}

// -------- scores + softmax, 4 t-rows per block, prefetched s-tiles --------
__global__ __launch_bounds__(512)
void scores_softmax_kernel(const float* __restrict__ v,
                           float* __restrict__ align_out)
{
    const int tg = blockIdx.x;
    const int b  = blockIdx.y;
    const int tid = threadIdx.x;
    const int warp = tid >> 5, lane = tid & 31;

    __shared__ float sa1[4][H_];
    __shared__ float ssc[4][S_];
    __shared__ float sred[17];

    #pragma unroll
    for (int i = 0; i < 4; i++)
        sa1[i][tid] = g_a1[((tg*4 + i)*B_ + b)*H_ + tid];

    float4 v0 = *(const float4*)(v + lane*4);
    float4 v1 = *(const float4*)(v + lane*4 + 128);
    float4 v2 = *(const float4*)(v + lane*4 + 256);
    float4 v3 = *(const float4*)(v + lane*4 + 384);
    __syncthreads();

    const float* a2base = g_a2 + (long)b*S_*H_ + lane*4;

    float4 x[4];
    {
        const float* p = a2base + (long)warp*H_;
        x[0] = *(const float4*)(p);
        x[1] = *(const float4*)(p + 128);
        x[2] = *(const float4*)(p + 256);
        x[3] = *(const float4*)(p + 384);
    }

    for (int s = warp; s < S_; s += 16) {
        float4 y[4];
        const int sn = s + 16;
        if (sn < S_) {
            const float* p = a2base + (long)sn*H_;
            y[0] = *(const float4*)(p);
            y[1] = *(const float4*)(p + 128);
            y[2] = *(const float4*)(p + 256);
            y[3] = *(const float4*)(p + 384);
        }

        #pragma unroll
        for (int i = 0; i < 4; i++) {
            float4 a0 = *(const float4*)(&sa1[i][lane*4]);
            float4 a1 = *(const float4*)(&sa1[i][lane*4 + 128]);
            float4 a2 = *(const float4*)(&sa1[i][lane*4 + 256]);
            float4 a3 = *(const float4*)(&sa1[i][lane*4 + 384]);
            float acc = 0.0f;
            acc = fmaf(tanhf_hw(a0.x + x[0].x), v0.x, acc);
            acc = fmaf(tanhf_hw(a0.y + x[0].y), v0.y, acc);
            acc = fmaf(tanhf_hw(a0.z + x[0].z), v0.z, acc);
            acc = fmaf(tanhf_hw(a0.w + x[0].w), v0.w, acc);
            acc = fmaf(tanhf_hw(a1.x + x[1].x), v1.x, acc);
            acc = fmaf(tanhf_hw(a1.y + x[1].y), v1.y, acc);
            acc = fmaf(tanhf_hw(a1.z + x[1].z), v1.z, acc);
            acc = fmaf(tanhf_hw(a1.w + x[1].w), v1.w, acc);
            acc = fmaf(tanhf_hw(a2.x + x[2].x), v2.x, acc);
            acc = fmaf(tanhf_hw(a2.y + x[2].y), v2.y, acc);
            acc = fmaf(tanhf_hw(a2.z + x[2].z), v2.z, acc);
            acc = fmaf(tanhf_hw(a2.w + x[2].w), v2.w, acc);
            acc = fmaf(tanhf_hw(a3.x + x[3].x), v3.x, acc);
            acc = fmaf(tanhf_hw(a3.y + x[3].y), v3.y, acc);
            acc = fmaf(tanhf_hw(a3.z + x[3].z), v3.z, acc);
            acc = fmaf(tanhf_hw(a3.w + x[3].w), v3.w, acc);
            #pragma unroll
            for (int o = 16; o > 0; o >>= 1)
                acc += __shfl_xor_sync(0xffffffffu, acc, o);
            if (lane == 0) ssc[i][s] = acc;
        }
        x[0] = y[0]; x[1] = y[1]; x[2] = y[2]; x[3] = y[3];
    }
    __syncthreads();

    #pragma unroll
    for (int i = 0; i < 4; i++) {
        float xx = ssc[i][tid];
        float m = xx;
        #pragma unroll
        for (int o = 16; o > 0; o >>= 1) m = fmaxf(m, __shfl_xor_sync(0xffffffffu, m, o));
        if (lane == 0) sred[warp] = m;
        __syncthreads();
        if (warp == 0) {
            float mm = (lane < 16) ? sred[lane] : -1e30f;
            #pragma unroll
            for (int o = 8; o > 0; o >>= 1) mm = fmaxf(mm, __shfl_xor_sync(0xffffffffu, mm, o));
            if (lane == 0) sred[16] = mm;
        }
        __syncthreads();
        const float mx = sred[16];
        float e = ex2f_((xx - mx) * 1.4426950408889634f);
        float ssum = e;
        #pragma unroll
        for (int o = 16; o > 0; o >>= 1) ssum += __shfl_xor_sync(0xffffffffu, ssum, o);
        __syncthreads();
        if (lane == 0) sred[warp] = ssum;
        __syncthreads();
        if (warp == 0) {
            float t = (lane < 16) ? sred[lane] : 0.0f;
            #pragma unroll
            for (int o = 8; o > 0; o >>= 1) t += __shfl_xor_sync(0xffffffffu, t, o);
            if (lane == 0) sred[16] = t;
        }
        __syncthreads();
        float p = e * rcpf_(sred[16]);
        align_out[(long)((tg*4 + i)*B_ + b)*S_ + tid] = p;
        __syncthreads();
    }
}

extern "C" void kernel_launch(void* const* d_in, const int* in_sizes, int n_in,
                              void* d_out, int out_size)
{
    const float* dec  = (const float*)d_in[0];
    const float* enc  = (const float*)d_in[1];
    const float* cov  = (const float*)d_in[2];
    const float* Wq   = (const float*)d_in[3];
    const float* bq   = (const float*)d_in[4];
    const float* Wc   = (const float*)d_in[5];
    const float* v    = (const float*)d_in[6];
    const float* Wo   = (const float*)d_in[7];
    const float* bo   = (const float*)d_in[8];
    const float* wcov = (const float*)d_in[9];

    float* attn_h = (float*)d_out;
    float* align  = (float*)d_out + TBH;

    static cudaStream_t s1 = nullptr;
    static cudaEvent_t evFork = nullptr, evJoin = nullptr;
    if (!s1) {
        cudaStreamCreateWithFlags(&s1, cudaStreamNonBlocking);
        cudaEventCreateWithFlags(&evFork, cudaEventDisableTiming);
        cudaEventCreateWithFlags(&evJoin, cudaEventDisableTiming);
    }

    // Side stream: dec@Wo2 partials (depend only on inputs).
    cudaEventRecord(evFork, 0);
    cudaStreamWaitEvent(s1, evFork, 0);
    out_splitk_d_kernel<<<dim3(8, 8, 4), 256, 0, s1>>>(dec, Wo);
    cudaEventRecord(evJoin, s1);

    // Main chain (prep fused into qc and c loaders).
    qc_gemm_kernel<<<144, 256>>>(enc, cov, wcov, Wc, dec, Wq, bq);
    scores_softmax_kernel<<<dim3(16, 8), 512>>>(v, align);
    c_splitk_kernel<<<dim3(8, 8, 4), 256>>>(align, enc, cov, wcov);
    out_splitk_c_kernel<<<dim3(8, 8, 4), 256>>>(Wo);

    cudaStreamWaitEvent(0, evJoin, 0);
    final_reduce_kernel<<<TBH/1024, 256>>>(attn_h, bo);
}